// round 14
// baseline (speedup 1.0000x reference)
#include <cuda_runtime.h>
#include <cuda_bf16.h>
#include <math.h>

#define BB 64
#define TT 512
#define HH 512
#define KTOT 1792        // W1(256)+U1(512)+W2(512)+U2(512)
#define AS 136           // A tile row stride (bf16): 128 k + 8 pad (272B, conflict-free ldsm)
#define HS 72            // H tile row stride (bf16): 64 b + 8 pad  (144B, conflict-free ldsm)
#define ATILE (32 * AS)  // 4352 bf16
#define HTILE (128 * HS) // 9216 bf16
#define SMEM_DYN ((4 * ATILE + 4 * HTILE) * 2 + 32 * 65 * 4)   // 116864 B

// ---------------- device scratch (allocation-free) ----------------
__device__ __nv_bfloat16 g_Wp[2][64][2][32 * KTOT];  // [dir][cta][hl][m][k]
__device__ __nv_bfloat16 g_Xp[TT][2][256 * 64];      // [t][hl][e][b]
__device__ __nv_bfloat16 g_hs[2][2][2][2][HH * 64];  // [dir][layer][par][hl][k][b]
__device__ float g_h2f[2][HH * 64];
__device__ unsigned g_bar[2];
__device__ int g_tok32;

// ---------------- helpers ----------------
__device__ __forceinline__ float fsig(float x) { return 1.0f / (1.0f + __expf(-x)); }
__device__ __forceinline__ float ftanh(float x) { return 2.0f / (1.0f + __expf(-2.0f * x)) - 1.0f; }
__device__ __forceinline__ unsigned smem_u32(const void* p) {
    unsigned a;
    asm("{ .reg .u64 t; cvta.to.shared.u64 t, %1; cvt.u32.u64 %0, t; }" : "=r"(a) : "l"(p));
    return a;
}
__device__ __forceinline__ void ldsm4(unsigned* r, unsigned a) {
    asm volatile("ldmatrix.sync.aligned.m8n8.x4.shared.b16 {%0,%1,%2,%3}, [%4];"
                 : "=r"(r[0]), "=r"(r[1]), "=r"(r[2]), "=r"(r[3]) : "r"(a));
}
__device__ __forceinline__ void ldsm2t(unsigned* r, unsigned a) {
    asm volatile("ldmatrix.sync.aligned.m8n8.x2.trans.shared.b16 {%0,%1}, [%2];"
                 : "=r"(r[0]), "=r"(r[1]) : "r"(a));
}
__device__ __forceinline__ void mma4(float* d, const unsigned* a, const unsigned* b) {
    asm volatile("mma.sync.aligned.m16n8k16.row.col.f32.bf16.bf16.f32 "
                 "{%0,%1,%2,%3}, {%4,%5,%6,%7}, {%8,%9}, {%0,%1,%2,%3};"
                 : "+f"(d[0]), "+f"(d[1]), "+f"(d[2]), "+f"(d[3])
                 : "r"(a[0]), "r"(a[1]), "r"(a[2]), "r"(a[3]), "r"(b[0]), "r"(b[1]));
}
__device__ __forceinline__ void grid_bar(unsigned* ctr, unsigned target) {
    __syncthreads();
    if (threadIdx.x == 0) {
        __threadfence();
        atomicAdd(ctr, 1u);
        while (*((volatile unsigned*)ctr) < target) { }
    }
    __syncthreads();
}

// ---------------- reset ----------------
__global__ void reset_kernel() {
    unsigned i = blockIdx.x * blockDim.x + threadIdx.x;
    unsigned* p = (unsigned*)g_hs;
    for (unsigned j = i; j < sizeof(g_hs) / 4; j += 32768) p[j] = 0;
    if (i == 0) { g_bar[0] = 0u; g_bar[1] = 0u; }
}

// ---------------- token dtype detect ----------------
__global__ void detect_kernel(const unsigned* tok) {
    __shared__ unsigned red[256];
    unsigned v = 0;
    for (int i = threadIdx.x; i < 16384; i += 256) v |= tok[2 * i + 1];
    red[threadIdx.x] = v;
    __syncthreads();
    for (int s = 128; s > 0; s >>= 1) {
        if (threadIdx.x < s) red[threadIdx.x] |= red[threadIdx.x + s];
        __syncthreads();
    }
    if (threadIdx.x == 0) g_tok32 = (red[0] != 0u) ? 1 : 0;
}

// ---------------- embedding gather -> [t][hl][e][b] bf16 ----------------
__global__ void gather_kernel(const void* tokens, const float* emb) {
    int t = blockIdx.x, eg = blockIdx.y;
    int wid = threadIdx.x >> 5, lane = threadIdx.x & 31;
    int e = eg * 8 + wid;
    #pragma unroll
    for (int j = 0; j < 2; j++) {
        int b = lane + j * 32;
        long idx;
        if (g_tok32) idx = (long)((const int*)tokens)[b * TT + t];
        else         idx = (long)((const unsigned*)tokens)[(size_t)(b * TT + t) * 2];
        float v = emb[idx * 256 + e];
        __nv_bfloat16 hi = __float2bfloat16(v);
        g_Xp[t][0][e * 64 + b] = hi;
        g_Xp[t][1][e * 64 + b] = __float2bfloat16(v - __bfloat162float(hi));
    }
}

// ---------------- weight prepack ----------------
__global__ void wpack_kernel(const float* W1f, const float* U1f, const float* W2f, const float* U2f,
                             const float* W1b, const float* U1b, const float* W2b, const float* U2b) {
    int cid = blockIdx.x & 63, dir = blockIdx.x >> 6;
    const float *W1 = dir ? W1b : W1f, *U1 = dir ? U1b : U1f;
    const float *W2 = dir ? W2b : W2f, *U2 = dir ? U2b : U2f;
    __nv_bfloat16* d0 = g_Wp[dir][cid][0];
    __nv_bfloat16* d1 = g_Wp[dir][cid][1];
    for (int idx = threadIdx.x; idx < 32 * KTOT; idx += 256) {
        int m = idx / KTOT, k = idx % KTOT;
        const float* M; int kk;
        if (k < 256)       { M = W1; kk = k; }
        else if (k < 768)  { M = U1; kk = k - 256; }
        else if (k < 1280) { M = W2; kk = k - 768; }
        else               { M = U2; kk = k - 1280; }
        int col = (m >> 3) * 512 + cid * 8 + (m & 7);
        float w = M[(size_t)kk * 2048 + col];
        __nv_bfloat16 hi = __float2bfloat16(w);
        d0[idx] = hi;
        d1[idx] = __float2bfloat16(w - __bfloat162float(hi));
    }
}

// ---------------- persistent HMMA BiLSTM (K=128 tiles, 512 threads) ----------------
__global__ void __launch_bounds__(512, 1) lstm_kernel(
    const float* __restrict__ b1f, const float* __restrict__ b2f,
    const float* __restrict__ b1b, const float* __restrict__ b2b)
{
    const int dir = blockIdx.x >> 6, cid = blockIdx.x & 63;
    const int ub = cid * 8;
    const int tid = threadIdx.x, lane = tid & 31, wid = tid >> 5;
    const int mbase = (wid & 1) * 16;        // 2 warps in M
    const int nbase = (wid >> 1) * 8;        // 8 warps in N (n8 each)

    extern __shared__ __nv_bfloat16 dsm[];
    __nv_bfloat16* sWb = dsm;                       // [buf][hl] x ATILE
    __nv_bfloat16* sHb = dsm + 4 * ATILE;           // [buf][hl] x HTILE
    float* zb = (float*)(dsm + 4 * ATILE + 4 * HTILE);

    const unsigned aWbase = smem_u32(sWb);
    const unsigned aHbase = smem_u32(sHb);
    // ldsm lane byte-offsets
    const unsigned a_off = ((mbase + ((lane >> 3) & 1) * 8 + (lane & 7)) * AS + (lane >> 4) * 8) * 2;
    const unsigned b_off = ((lane & 15) * HS + nbase) * 2;

    const float* b1 = dir ? b1b : b1f;
    const float* b2 = dir ? b2b : b2f;
    const int pu = tid >> 6;           // unit 0..7
    const int pb = tid & 63;           // batch 0..63
    float bias1[4], bias2[4];
    #pragma unroll
    for (int g = 0; g < 4; g++) {
        bias1[g] = b1[g * 512 + ub + pu];
        bias2[g] = b2[g * 512 + ub + pu];
    }

    const __nv_bfloat16* Wp0 = g_Wp[dir][cid][0];
    const __nv_bfloat16* Wp1 = g_Wp[dir][cid][1];
    const int wrow = tid >> 4, wcol = (tid & 15) * 8;   // A staging
    const int hrow = tid >> 3, hcol = (tid & 7) * 8;    // H staging (rows hrow, hrow+64)

    float c1 = 0.f, c2 = 0.f;
    unsigned target = 0;

    for (int t = 0; t < TT; t++) {
        const int ttx = dir ? (TT - 1 - t) : t;
        const int wp = t & 1, rp = wp ^ 1;
        for (int ph = 0; ph < 2; ph++) {
            float dn[4] = {0.f, 0.f, 0.f, 0.f};
            const int nch = ph ? 8 : 6;

            auto src_of = [&](int c, int& kofs, const __nv_bfloat16*& s0, const __nv_bfloat16*& s1) {
                if (ph == 0) {
                    if (c < 2) { kofs = c * 128;             s0 = g_Xp[ttx][0] + c * 8192;              s1 = g_Xp[ttx][1] + c * 8192; }
                    else       { kofs = 256 + (c - 2) * 128; s0 = g_hs[dir][0][rp][0] + (c - 2) * 8192; s1 = g_hs[dir][0][rp][1] + (c - 2) * 8192; }
                } else {
                    if (c < 4) { kofs = 768 + c * 128;        s0 = g_hs[dir][0][wp][0] + c * 8192;       s1 = g_hs[dir][0][wp][1] + c * 8192; }
                    else       { kofs = 1280 + (c - 4) * 128; s0 = g_hs[dir][1][rp][0] + (c - 4) * 8192; s1 = g_hs[dir][1][rp][1] + (c - 4) * 8192; }
                }
            };

            // ---- prologue: stage chunk 0 into buf 0 ----
            {
                int kofs; const __nv_bfloat16 *bs0, *bs1;
                src_of(0, kofs, bs0, bs1);
                float4 w0 = *(const float4*)(Wp0 + (size_t)wrow * KTOT + kofs + wcol);
                float4 w1 = *(const float4*)(Wp1 + (size_t)wrow * KTOT + kofs + wcol);
                float4 ha0 = __ldcg((const float4*)(bs0 + tid * 8));
                float4 ha1 = __ldcg((const float4*)(bs0 + 4096 + tid * 8));
                float4 hb0 = __ldcg((const float4*)(bs1 + tid * 8));
                float4 hb1 = __ldcg((const float4*)(bs1 + 4096 + tid * 8));
                *(float4*)&sWb[0 * ATILE + wrow * AS + wcol] = w0;
                *(float4*)&sWb[1 * ATILE + wrow * AS + wcol] = w1;
                *(float4*)&sHb[0 * HTILE + hrow * HS + hcol] = ha0;
                *(float4*)&sHb[0 * HTILE + (hrow + 64) * HS + hcol] = ha1;
                *(float4*)&sHb[1 * HTILE + hrow * HS + hcol] = hb0;
                *(float4*)&sHb[1 * HTILE + (hrow + 64) * HS + hcol] = hb1;
                __syncthreads();
            }

            for (int c = 0; c < nch; c++) {
                const int buf = c & 1, nbuf = buf ^ 1;
                float4 w0, w1, ha0, ha1, hb0, hb1;
                const bool more = (c + 1 < nch);
                if (more) {
                    int kofs; const __nv_bfloat16 *bs0, *bs1;
                    src_of(c + 1, kofs, bs0, bs1);
                    w0 = *(const float4*)(Wp0 + (size_t)wrow * KTOT + kofs + wcol);
                    w1 = *(const float4*)(Wp1 + (size_t)wrow * KTOT + kofs + wcol);
                    ha0 = __ldcg((const float4*)(bs0 + tid * 8));
                    ha1 = __ldcg((const float4*)(bs0 + 4096 + tid * 8));
                    hb0 = __ldcg((const float4*)(bs1 + tid * 8));
                    hb1 = __ldcg((const float4*)(bs1 + 4096 + tid * 8));
                }
                const unsigned aW0 = aWbase + (buf * 2 + 0) * ATILE * 2;
                const unsigned aW1 = aWbase + (buf * 2 + 1) * ATILE * 2;
                const unsigned aH0 = aHbase + (buf * 2 + 0) * HTILE * 2;
                const unsigned aH1 = aHbase + (buf * 2 + 1) * HTILE * 2;
                #pragma unroll
                for (int k16 = 0; k16 < 8; k16++) {
                    unsigned ah[4], al[4], bh[2], bl[2];
                    ldsm4(ah, aW0 + a_off + k16 * 32);
                    ldsm4(al, aW1 + a_off + k16 * 32);
                    ldsm2t(bh, aH0 + b_off + k16 * 16 * HS * 2);
                    ldsm2t(bl, aH1 + b_off + k16 * 16 * HS * 2);
                    mma4(dn, ah, bh);
                    mma4(dn, al, bh);
                    mma4(dn, ah, bl);
                }
                if (more) {
                    *(float4*)&sWb[(nbuf * 2 + 0) * ATILE + wrow * AS + wcol] = w0;
                    *(float4*)&sWb[(nbuf * 2 + 1) * ATILE + wrow * AS + wcol] = w1;
                    *(float4*)&sHb[(nbuf * 2 + 0) * HTILE + hrow * HS + hcol] = ha0;
                    *(float4*)&sHb[(nbuf * 2 + 0) * HTILE + (hrow + 64) * HS + hcol] = ha1;
                    *(float4*)&sHb[(nbuf * 2 + 1) * HTILE + hrow * HS + hcol] = hb0;
                    *(float4*)&sHb[(nbuf * 2 + 1) * HTILE + (hrow + 64) * HS + hcol] = hb1;
                }
                __syncthreads();
            }
            // ---------- epilogue: accums -> zb ----------
            {
                int r = lane >> 2, cp = (lane & 3) * 2;
                zb[(mbase + r) * 65 + nbase + cp]         = dn[0];
                zb[(mbase + r) * 65 + nbase + cp + 1]     = dn[1];
                zb[(mbase + 8 + r) * 65 + nbase + cp]     = dn[2];
                zb[(mbase + 8 + r) * 65 + nbase + cp + 1] = dn[3];
            }
            __syncthreads();
            // ---------- pointwise (one cell per thread) ----------
            {
                const float* bias = ph ? bias2 : bias1;
                float iv = zb[pu * 65 + pb]        + bias[0];
                float fv = zb[(8 + pu) * 65 + pb]  + bias[1];
                float gv = zb[(16 + pu) * 65 + pb] + bias[2];
                float ov = zb[(24 + pu) * 65 + pb] + bias[3];
                float& cc = ph ? c2 : c1;
                cc = fsig(fv) * cc + fsig(iv) * ftanh(gv);
                float h = fsig(ov) * ftanh(cc);
                __nv_bfloat16 hi = __float2bfloat16(h);
                g_hs[dir][ph][wp][0][(ub + pu) * 64 + pb] = hi;
                g_hs[dir][ph][wp][1][(ub + pu) * 64 + pb] = __float2bfloat16(h - __bfloat162float(hi));
                if (ph && t == TT - 1) g_h2f[dir][(ub + pu) * 64 + pb] = h;
            }
            target += 64;
            grid_bar(&g_bar[dir], target);
        }
    }
}

// ---------------- final dense head ----------------
__global__ void dense_kernel(const float* __restrict__ Wd, const float* __restrict__ bd,
                             float* __restrict__ out) {
    int tid = threadIdx.x;
    if (tid >= 320) return;
    int b = tid / 5, o = tid % 5;
    float s = bd[o];
    for (int j = 0; j < HH; j++) s += g_h2f[0][j * 64 + b] * Wd[j * 5 + o];
    for (int j = 0; j < HH; j++) s += g_h2f[1][j * 64 + b] * Wd[(HH + j) * 5 + o];
    out[b * 5 + o] = s;
}

// ---------------- launch ----------------
extern "C" void kernel_launch(void* const* d_in, const int* in_sizes, int n_in,
                              void* d_out, int out_size) {
    const void*  tokens = d_in[0];
    const float* emb = (const float*)d_in[1];
    const float* W1f = (const float*)d_in[2];
    const float* U1f = (const float*)d_in[3];
    const float* b1f = (const float*)d_in[4];
    const float* W2f = (const float*)d_in[5];
    const float* U2f = (const float*)d_in[6];
    const float* b2f = (const float*)d_in[7];
    const float* W1b = (const float*)d_in[8];
    const float* U1b = (const float*)d_in[9];
    const float* b1b = (const float*)d_in[10];
    const float* W2b = (const float*)d_in[11];
    const float* U2b = (const float*)d_in[12];
    const float* b2b = (const float*)d_in[13];
    const float* Wd  = (const float*)d_in[14];
    const float* bd  = (const float*)d_in[15];
    float* out = (float*)d_out;

    cudaFuncSetAttribute(lstm_kernel, cudaFuncAttributeMaxDynamicSharedMemorySize, SMEM_DYN);
    reset_kernel<<<128, 256>>>();
    detect_kernel<<<1, 256>>>((const unsigned*)tokens);
    dim3 gg(TT, 32);
    gather_kernel<<<gg, 256>>>(tokens, emb);
    wpack_kernel<<<128, 256>>>(W1f, U1f, W2f, U2f, W1b, U1b, W2b, U2b);
    lstm_kernel<<<128, 512, SMEM_DYN>>>(b1f, b2f, b1b, b2b);
    dense_kernel<<<1, 320>>>(Wd, bd, out);
}

// round 17
// speedup vs baseline: 1.4455x; 1.4455x over previous
#include <cuda_runtime.h>
#include <cuda_bf16.h>
#include <math.h>

#define BB 64
#define TT 512
#define HH 512
#define WS 72            // smem row stride in bf16 (144B, conflict-free ldsm)
#define K1 768           // layer-1 K: x(256) + h1(512)
#define K2 1024          // layer-2 K: h1(512) + h2(512)
#define ATILE (64 * WS)  // 4608 bf16 per (hl,buf)
#define HTILE (64 * WS)
#define SMEM_DYN ((4 * ATILE + 4 * HTILE) * 2 + 64 * 65 * 4)   // 90368 B

// ---------------- device scratch (allocation-free) ----------------
__device__ __nv_bfloat16 g_Wp1[2][32][2][64 * K1];   // [dir][slice][hl][m][k]
__device__ __nv_bfloat16 g_Wp2[2][32][2][64 * K2];
__device__ __nv_bfloat16 g_Xp[TT][2][256 * 64];      // [t][hl][e][b]
__device__ __nv_bfloat16 g_hs[2][2][2][2][HH * 64];  // [dir][layer][par][hl][k][b]
__device__ float g_h2f[2][HH * 64];
__device__ unsigned g_bar[2];
__device__ int g_tok32;

// ---------------- helpers ----------------
__device__ __forceinline__ float fsig(float x) { return 1.0f / (1.0f + __expf(-x)); }
__device__ __forceinline__ float ftanh(float x) { return 2.0f / (1.0f + __expf(-2.0f * x)) - 1.0f; }
__device__ __forceinline__ unsigned smem_u32(const void* p) {
    unsigned a;
    asm("{ .reg .u64 t; cvta.to.shared.u64 t, %1; cvt.u32.u64 %0, t; }" : "=r"(a) : "l"(p));
    return a;
}
__device__ __forceinline__ void ldsm4(unsigned* r, unsigned a) {
    asm volatile("ldmatrix.sync.aligned.m8n8.x4.shared.b16 {%0,%1,%2,%3}, [%4];"
                 : "=r"(r[0]), "=r"(r[1]), "=r"(r[2]), "=r"(r[3]) : "r"(a));
}
__device__ __forceinline__ void ldsm4t(unsigned* r, unsigned a) {
    asm volatile("ldmatrix.sync.aligned.m8n8.x4.trans.shared.b16 {%0,%1,%2,%3}, [%4];"
                 : "=r"(r[0]), "=r"(r[1]), "=r"(r[2]), "=r"(r[3]) : "r"(a));
}
__device__ __forceinline__ void mma4(float* d, const unsigned* a, const unsigned* b) {
    asm volatile("mma.sync.aligned.m16n8k16.row.col.f32.bf16.bf16.f32 "
                 "{%0,%1,%2,%3}, {%4,%5,%6,%7}, {%8,%9}, {%0,%1,%2,%3};"
                 : "+f"(d[0]), "+f"(d[1]), "+f"(d[2]), "+f"(d[3])
                 : "r"(a[0]), "r"(a[1]), "r"(a[2]), "r"(a[3]), "r"(b[0]), "r"(b[1]));
}
__device__ __forceinline__ void grid_bar(unsigned* ctr, unsigned target) {
    __syncthreads();
    if (threadIdx.x == 0) {
        __threadfence();
        atomicAdd(ctr, 1u);
        while (*((volatile unsigned*)ctr) < target) { }
    }
    __syncthreads();
}

// ---------------- reset ----------------
__global__ void reset_kernel() {
    unsigned i = blockIdx.x * blockDim.x + threadIdx.x;
    unsigned* p = (unsigned*)g_hs;
    for (unsigned j = i; j < sizeof(g_hs) / 4; j += 32768) p[j] = 0;
    if (i == 0) { g_bar[0] = 0u; g_bar[1] = 0u; }
}

// ---------------- token dtype detect ----------------
__global__ void detect_kernel(const unsigned* tok) {
    __shared__ unsigned red[256];
    unsigned v = 0;
    for (int i = threadIdx.x; i < 16384; i += 256) v |= tok[2 * i + 1];
    red[threadIdx.x] = v;
    __syncthreads();
    for (int s = 128; s > 0; s >>= 1) {
        if (threadIdx.x < s) red[threadIdx.x] |= red[threadIdx.x + s];
        __syncthreads();
    }
    if (threadIdx.x == 0) g_tok32 = (red[0] != 0u) ? 1 : 0;
}

// ---------------- embedding gather -> [t][hl][e][b] bf16 ----------------
__global__ void gather_kernel(const void* tokens, const float* emb) {
    int t = blockIdx.x, eg = blockIdx.y;
    int wid = threadIdx.x >> 5, lane = threadIdx.x & 31;
    int e = eg * 8 + wid;
    #pragma unroll
    for (int j = 0; j < 2; j++) {
        int b = lane + j * 32;
        long idx;
        if (g_tok32) idx = (long)((const int*)tokens)[b * TT + t];
        else         idx = (long)((const unsigned*)tokens)[(size_t)(b * TT + t) * 2];
        float v = emb[idx * 256 + e];
        __nv_bfloat16 hi = __float2bfloat16(v);
        g_Xp[t][0][e * 64 + b] = hi;
        g_Xp[t][1][e * 64 + b] = __float2bfloat16(v - __bfloat162float(hi));
    }
}

// ---------------- weight prepack: per (dir, layer, slice) ----------------
__global__ void wpack_kernel(const float* W1f, const float* U1f, const float* W2f, const float* U2f,
                             const float* W1b, const float* U1b, const float* W2b, const float* U2b) {
    int blk = blockIdx.x;
    int sl = blk & 31, L = (blk >> 5) & 1, dir = blk >> 6;
    const float *Ma, *Mb;
    int KL, split;
    if (L == 0) { Ma = dir ? W1b : W1f; Mb = dir ? U1b : U1f; KL = K1; split = 256; }
    else        { Ma = dir ? W2b : W2f; Mb = dir ? U2b : U2f; KL = K2; split = 512; }
    __nv_bfloat16* d0 = L ? g_Wp2[dir][sl][0] : g_Wp1[dir][sl][0];
    __nv_bfloat16* d1 = L ? g_Wp2[dir][sl][1] : g_Wp1[dir][sl][1];
    for (int idx = threadIdx.x; idx < 64 * KL; idx += 256) {
        int m = idx / KL, k = idx % KL;
        const float* M = (k < split) ? Ma : Mb;
        int kk = (k < split) ? k : k - split;
        int col = (m >> 4) * 512 + sl * 16 + (m & 15);   // gate*512 + unit
        float w = M[(size_t)kk * 2048 + col];
        __nv_bfloat16 hi = __float2bfloat16(w);
        d0[idx] = hi;
        d1[idx] = __float2bfloat16(w - __bfloat162float(hi));
    }
}

// ---------------- persistent pipelined HMMA BiLSTM ----------------
// 128 CTAs = dir(2) x layer(2) x slice(32). Layer 2 runs one tick behind layer 1.
__global__ void __launch_bounds__(256, 1) lstm_kernel(
    const float* __restrict__ b1f, const float* __restrict__ b2f,
    const float* __restrict__ b1b, const float* __restrict__ b2b)
{
    const int dir = blockIdx.x >> 6;
    const int L   = (blockIdx.x >> 5) & 1;
    const int sl  = blockIdx.x & 31;
    const int ub  = sl * 16;
    const int tid = threadIdx.x, lane = tid & 31, wid = tid >> 5;
    const int mbase = (wid & 3) * 16;        // 4 warps in M=64
    const int nbase = (wid >> 2) * 32;       // 2 warps in N=64 (n32 each)

    extern __shared__ __nv_bfloat16 dsm[];
    __nv_bfloat16* sWb = dsm;                       // [buf][hl] x ATILE
    __nv_bfloat16* sHb = dsm + 4 * ATILE;           // [buf][hl] x HTILE
    float* zb = (float*)(dsm + 4 * ATILE + 4 * HTILE);   // [64 m][65]

    const unsigned aWbase = smem_u32(sWb);
    const unsigned aHbase = smem_u32(sHb);
    const unsigned a_off = ((mbase + ((lane >> 3) & 1) * 8 + (lane & 7)) * WS + (lane >> 4) * 8) * 2;
    const unsigned b_off = ((((lane >> 3) & 1) * 8 + (lane & 7)) * WS + nbase + (lane >> 4) * 8) * 2;

    const float* bL = L ? (dir ? b2b : b2f) : (dir ? b1b : b1f);
    const int uu = tid >> 6;           // 0..3 -> units uu+4j
    const int pb = tid & 63;
    float bias[4][4];                  // [gate][j]
    #pragma unroll
    for (int g = 0; g < 4; g++)
        #pragma unroll
        for (int j = 0; j < 4; j++)
            bias[g][j] = bL[g * 512 + ub + uu + j * 4];

    const __nv_bfloat16* WpH = L ? g_Wp2[dir][sl][0] : g_Wp1[dir][sl][0];
    const __nv_bfloat16* WpL = L ? g_Wp2[dir][sl][1] : g_Wp1[dir][sl][1];
    const int KL = L ? K2 : K1;
    const int nch = L ? 16 : 12;

    const int arow = tid >> 3, aseg = (tid & 7) * 8;   // A staging rows arow, arow+32
    const int hrow = tid >> 3, hcol = (tid & 7) * 8;   // H staging rows hrow, hrow+32

    float cc[4];
    #pragma unroll
    for (int j = 0; j < 4; j++) cc[j] = 0.f;
    unsigned target = 0;

    for (int tick = 0; tick <= TT; tick++) {
        const bool active = L ? (tick >= 1) : (tick < TT);
        if (active) {
            const int t = L ? (tick - 1) : tick;       // time index this CTA computes
            const int wpar = t & 1;
            const int ttx = dir ? (TT - 1 - t) : t;

            auto src_of = [&](int c, const __nv_bfloat16*& s0, const __nv_bfloat16*& s1) {
                if (L == 0) {
                    if (c < 4) { s0 = g_Xp[ttx][0] + c * 4096;                  s1 = g_Xp[ttx][1] + c * 4096; }
                    else       { s0 = g_hs[dir][0][wpar ^ 1][0] + (c - 4) * 4096; s1 = g_hs[dir][0][wpar ^ 1][1] + (c - 4) * 4096; }
                } else {
                    if (c < 8) { s0 = g_hs[dir][0][wpar][0] + c * 4096;           s1 = g_hs[dir][0][wpar][1] + c * 4096; }
                    else       { s0 = g_hs[dir][1][wpar ^ 1][0] + (c - 8) * 4096; s1 = g_hs[dir][1][wpar ^ 1][1] + (c - 8) * 4096; }
                }
            };

            float d0[4] = {0.f,0.f,0.f,0.f}, d1[4] = {0.f,0.f,0.f,0.f};
            float d2[4] = {0.f,0.f,0.f,0.f}, d3[4] = {0.f,0.f,0.f,0.f};

            // ---- prologue: stage chunk 0 into buf 0 ----
            {
                const __nv_bfloat16 *bs0, *bs1;
                src_of(0, bs0, bs1);
                const __nv_bfloat16* aH = WpH + (size_t)arow * KL + aseg;
                const __nv_bfloat16* aL = WpL + (size_t)arow * KL + aseg;
                float4 w00 = *(const float4*)aH;
                float4 w01 = *(const float4*)(aH + (size_t)32 * KL);
                float4 w10 = *(const float4*)aL;
                float4 w11 = *(const float4*)(aL + (size_t)32 * KL);
                float4 ha0 = __ldcg((const float4*)(bs0 + tid * 8));
                float4 ha1 = __ldcg((const float4*)(bs0 + 2048 + tid * 8));
                float4 hb0 = __ldcg((const float4*)(bs1 + tid * 8));
                float4 hb1 = __ldcg((const float4*)(bs1 + 2048 + tid * 8));
                *(float4*)&sWb[0 * ATILE + arow * WS + aseg] = w00;
                *(float4*)&sWb[0 * ATILE + (arow + 32) * WS + aseg] = w01;
                *(float4*)&sWb[1 * ATILE + arow * WS + aseg] = w10;
                *(float4*)&sWb[1 * ATILE + (arow + 32) * WS + aseg] = w11;
                *(float4*)&sHb[0 * HTILE + hrow * WS + hcol] = ha0;
                *(float4*)&sHb[0 * HTILE + (hrow + 32) * WS + hcol] = ha1;
                *(float4*)&sHb[1 * HTILE + hrow * WS + hcol] = hb0;
                *(float4*)&sHb[1 * HTILE + (hrow + 32) * WS + hcol] = hb1;
                __syncthreads();
            }

            for (int c = 0; c < nch; c++) {
                const int buf = c & 1, nbuf = buf ^ 1;
                float4 w00, w01, w10, w11, ha0, ha1, hb0, hb1;
                const bool more = (c + 1 < nch);
                if (more) {
                    const __nv_bfloat16 *bs0, *bs1;
                    src_of(c + 1, bs0, bs1);
                    int kofs = (c + 1) * 64;
                    const __nv_bfloat16* aH = WpH + (size_t)arow * KL + kofs + aseg;
                    const __nv_bfloat16* aL = WpL + (size_t)arow * KL + kofs + aseg;
                    w00 = *(const float4*)aH;
                    w01 = *(const float4*)(aH + (size_t)32 * KL);
                    w10 = *(const float4*)aL;
                    w11 = *(const float4*)(aL + (size_t)32 * KL);
                    ha0 = __ldcg((const float4*)(bs0 + tid * 8));
                    ha1 = __ldcg((const float4*)(bs0 + 2048 + tid * 8));
                    hb0 = __ldcg((const float4*)(bs1 + tid * 8));
                    hb1 = __ldcg((const float4*)(bs1 + 2048 + tid * 8));
                }
                const unsigned aW0 = aWbase + (buf * 2 + 0) * ATILE * 2;
                const unsigned aW1 = aWbase + (buf * 2 + 1) * ATILE * 2;
                const unsigned aH0 = aHbase + (buf * 2 + 0) * HTILE * 2;
                const unsigned aH1 = aHbase + (buf * 2 + 1) * HTILE * 2;
                #pragma unroll
                for (int k16 = 0; k16 < 4; k16++) {
                    unsigned ah[4], al[4], bh0[4], bh1[4], bl0[4], bl1[4];
                    ldsm4(ah, aW0 + a_off + k16 * 32);
                    ldsm4(al, aW1 + a_off + k16 * 32);
                    ldsm4t(bh0, aH0 + b_off + k16 * 16 * WS * 2);
                    ldsm4t(bh1, aH0 + b_off + 32 + k16 * 16 * WS * 2);
                    ldsm4t(bl0, aH1 + b_off + k16 * 16 * WS * 2);
                    ldsm4t(bl1, aH1 + b_off + 32 + k16 * 16 * WS * 2);
                    mma4(d0, ah, bh0); mma4(d1, ah, bh0 + 2);
                    mma4(d2, ah, bh1); mma4(d3, ah, bh1 + 2);
                    mma4(d0, al, bh0); mma4(d1, al, bh0 + 2);
                    mma4(d2, al, bh1); mma4(d3, al, bh1 + 2);
                    mma4(d0, ah, bl0); mma4(d1, ah, bl0 + 2);
                    mma4(d2, ah, bl1); mma4(d3, ah, bl1 + 2);
                }
                if (more) {
                    *(float4*)&sWb[(nbuf * 2 + 0) * ATILE + arow * WS + aseg] = w00;
                    *(float4*)&sWb[(nbuf * 2 + 0) * ATILE + (arow + 32) * WS + aseg] = w01;
                    *(float4*)&sWb[(nbuf * 2 + 1) * ATILE + arow * WS + aseg] = w10;
                    *(float4*)&sWb[(nbuf * 2 + 1) * ATILE + (arow + 32) * WS + aseg] = w11;
                    *(float4*)&sHb[(nbuf * 2 + 0) * HTILE + hrow * WS + hcol] = ha0;
                    *(float4*)&sHb[(nbuf * 2 + 0) * HTILE + (hrow + 32) * WS + hcol] = ha1;
                    *(float4*)&sHb[(nbuf * 2 + 1) * HTILE + hrow * WS + hcol] = hb0;
                    *(float4*)&sHb[(nbuf * 2 + 1) * HTILE + (hrow + 32) * WS + hcol] = hb1;
                }
                __syncthreads();
            }
            // ---------- epilogue: accums -> zb ----------
            {
                int r = lane >> 2, cp = (lane & 3) * 2;
                float* dj[4] = {d0, d1, d2, d3};
                #pragma unroll
                for (int j = 0; j < 4; j++) {
                    int col = nbase + j * 8 + cp;
                    zb[(mbase + r) * 65 + col]     = dj[j][0];
                    zb[(mbase + r) * 65 + col + 1] = dj[j][1];
                    zb[(mbase + 8 + r) * 65 + col]     = dj[j][2];
                    zb[(mbase + 8 + r) * 65 + col + 1] = dj[j][3];
                }
            }
            __syncthreads();
            // ---------- pointwise: 4 cells per thread ----------
            {
                __nv_bfloat16* h0 = g_hs[dir][L][wpar][0];
                __nv_bfloat16* h1 = g_hs[dir][L][wpar][1];
                #pragma unroll
                for (int j = 0; j < 4; j++) {
                    int u = uu + j * 4;
                    float iv = zb[(u)      * 65 + pb] + bias[0][j];
                    float fv = zb[(16 + u) * 65 + pb] + bias[1][j];
                    float gv = zb[(32 + u) * 65 + pb] + bias[2][j];
                    float ov = zb[(48 + u) * 65 + pb] + bias[3][j];
                    cc[j] = fsig(fv) * cc[j] + fsig(iv) * ftanh(gv);
                    float h = fsig(ov) * ftanh(cc[j]);
                    __nv_bfloat16 hi = __float2bfloat16(h);
                    h0[(ub + u) * 64 + pb] = hi;
                    h1[(ub + u) * 64 + pb] = __float2bfloat16(h - __bfloat162float(hi));
                    if (L && t == TT - 1) g_h2f[dir][(ub + u) * 64 + pb] = h;
                }
            }
        }
        target += 64;
        grid_bar(&g_bar[dir], target);
    }
}

// ---------------- final dense head ----------------
__global__ void dense_kernel(const float* __restrict__ Wd, const float* __restrict__ bd,
                             float* __restrict__ out) {
    int tid = threadIdx.x;
    if (tid >= 320) return;
    int b = tid / 5, o = tid % 5;
    float s = bd[o];
    for (int j = 0; j < HH; j++) s += g_h2f[0][j * 64 + b] * Wd[j * 5 + o];
    for (int j = 0; j < HH; j++) s += g_h2f[1][j * 64 + b] * Wd[(HH + j) * 5 + o];
    out[b * 5 + o] = s;
}

// ---------------- launch ----------------
extern "C" void kernel_launch(void* const* d_in, const int* in_sizes, int n_in,
                              void* d_out, int out_size) {
    const void*  tokens = d_in[0];
    const float* emb = (const float*)d_in[1];
    const float* W1f = (const float*)d_in[2];
    const float* U1f = (const float*)d_in[3];
    const float* b1f = (const float*)d_in[4];
    const float* W2f = (const float*)d_in[5];
    const float* U2f = (const float*)d_in[6];
    const float* b2f = (const float*)d_in[7];
    const float* W1b = (const float*)d_in[8];
    const float* U1b = (const float*)d_in[9];
    const float* b1b = (const float*)d_in[10];
    const float* W2b = (const float*)d_in[11];
    const float* U2b = (const float*)d_in[12];
    const float* b2b = (const float*)d_in[13];
    const float* Wd  = (const float*)d_in[14];
    const float* bd  = (const float*)d_in[15];
    float* out = (float*)d_out;

    cudaFuncSetAttribute(lstm_kernel, cudaFuncAttributeMaxDynamicSharedMemorySize, SMEM_DYN);
    reset_kernel<<<128, 256>>>();
    detect_kernel<<<1, 256>>>((const unsigned*)tokens);
    dim3 gg(TT, 32);
    gather_kernel<<<gg, 256>>>(tokens, emb);
    wpack_kernel<<<128, 256>>>(W1f, U1f, W2f, U2f, W1b, U1b, W2b, U2b);
    lstm_kernel<<<128, 256, SMEM_DYN>>>(b1f, b2f, b1b, b2b);
    dense_kernel<<<1, 320>>>(Wd, bd, out);
}